// round 3
// baseline (speedup 1.0000x reference)
#include <cuda_runtime.h>
#include <cuda_bf16.h>
#include <cstdint>

// Problem constants
#define BB 4
#define NN 4096
#define CC 64
#define BN (BB * NN)

#define TARGETF 560.0f
#define MIN_BOXF 5.0f
#define IOU_THRF 0.2f
#define CONF_THRF 0.001f
#define BOX_CONF_THRF 0.01f
#define MAX_WHF 4096.0f

#define CAP 256                    // per-class member cap for fast path
#define WSTRIDE 8                  // mask words per row (CAP/32)

// ------------------------- scratch (static device memory) -------------------
__device__ float4 g_cbox[BN];                      // clipped boxes, orig order
__device__ float  g_key[BN];                       // valid ? conf : -1
__device__ __align__(128) unsigned char g_tag[BN]; // valid ? cls : 255
__device__ float  g_kept[BB * NN * 8];             // kept entries (8 floats)
__device__ int    g_kcnt[BB];

// ------------------------- K0: zero output + counters -----------------------
__global__ void k0_zero(float* out, int n) {
    int i = blockIdx.x * blockDim.x + threadIdx.x;
    if (i < n) out[i] = 0.0f;
    if (i < BB) g_kcnt[i] = 0;
}

// ------------------------- K1: conf / argmax / clip / valid -----------------
__global__ void k1_prepare(const float* __restrict__ boxes,
                           const float* __restrict__ scores,
                           const float* __restrict__ preds) {
    int box  = (blockIdx.x * blockDim.x + threadIdx.x) >> 5;
    int lane = threadIdx.x & 31;
    if (box >= BN) return;

    const float* p = preds + (size_t)box * CC;
    float s = scores[box];

    float v0 = __fmul_rn(p[lane], s);
    float v1 = __fmul_rn(p[lane + 32], s);
    float bv; int bi;
    if (v1 > v0) { bv = v1; bi = lane + 32; } else { bv = v0; bi = lane; }

    #pragma unroll
    for (int o = 16; o > 0; o >>= 1) {
        float ov = __shfl_down_sync(0xffffffffu, bv, o);
        int   oi = __shfl_down_sync(0xffffffffu, bi, o);
        if (ov > bv || (ov == bv && oi < bi)) { bv = ov; bi = oi; }
    }

    if (lane == 0) {
        float4 bx = reinterpret_cast<const float4*>(boxes)[box];
        float x1 = fminf(fmaxf(bx.x, 0.0f), TARGETF);
        float y1 = fminf(fmaxf(bx.y, 0.0f), TARGETF);
        float x2 = fminf(fmaxf(bx.z, 0.0f), TARGETF);
        float y2 = fminf(fmaxf(bx.w, 0.0f), TARGETF);
        float w = __fsub_rn(x2, x1);
        float h = __fsub_rn(y2, y1);
        int valid = (s > BOX_CONF_THRF) && (w > MIN_BOXF) && (h > MIN_BOXF)
                    && (bv > CONF_THRF);
        g_cbox[box] = make_float4(x1, y1, x2, y2);
        g_key[box]  = valid ? bv : -1.0f;
        g_tag[box]  = valid ? (unsigned char)bi : (unsigned char)255;
    }
}

// ------------------------- K2: per-(batch,class) NMS ------------------------
// 128 threads. Compact members (original idx order) -> local stable sort by
// (conf desc, idx asc) -> smem-resident pairwise IoU bit-matrix -> greedy
// bitmask scan -> append kept entries to g_kept via atomic slot.
__global__ void __launch_bounds__(128) k2_nms() {
    int bc   = blockIdx.x;
    int b    = bc >> 6;
    int c    = bc & 63;
    int t    = threadIdx.x;
    int lane = t & 31;
    int wid  = t >> 5;

    __shared__ unsigned long long skey[CAP];                  // 2KB
    __shared__ float sx1[CAP], sy1[CAP], sx2[CAP], sy2[CAP];  // 4KB
    __shared__ float sar[CAP], scf[CAP];                      // 2KB
    __shared__ int   spos[CAP];                               // 1KB
    __shared__ unsigned int smask[CAP * WSTRIDE];             // 8KB
    __shared__ int   flist[NN];                               // 16KB (full list)
    __shared__ unsigned char fsup[NN];                        // 4KB (fallback)
    __shared__ int   warp_tot[5];
    __shared__ float rbk[128]; __shared__ int rbm[128];       // fallback reduce
    __shared__ float bbox[8];  __shared__ int bflag[1];

    // ---- Stage 1: compaction (thread t covers positions [t*32, t*32+32)) ---
    const uint4* tw = reinterpret_cast<const uint4*>(g_tag + b * NN);
    uint4 wa = tw[t * 2], wb = tw[t * 2 + 1];
    unsigned int cls4 = (unsigned int)c * 0x01010101u;
    unsigned int eq[8];
    eq[0] = __vcmpeq4(wa.x, cls4); eq[1] = __vcmpeq4(wa.y, cls4);
    eq[2] = __vcmpeq4(wa.z, cls4); eq[3] = __vcmpeq4(wa.w, cls4);
    eq[4] = __vcmpeq4(wb.x, cls4); eq[5] = __vcmpeq4(wb.y, cls4);
    eq[6] = __vcmpeq4(wb.z, cls4); eq[7] = __vcmpeq4(wb.w, cls4);
    int cnt = 0;
    #pragma unroll
    for (int w = 0; w < 8; w++) cnt += __popc(eq[w]) >> 3;

    // block exclusive scan
    int inc = cnt;
    #pragma unroll
    for (int o = 1; o < 32; o <<= 1) {
        int tmp = __shfl_up_sync(0xffffffffu, inc, o);
        if (lane >= o) inc += tmp;
    }
    if (lane == 31) warp_tot[wid] = inc;
    __syncthreads();
    if (t == 0) {
        int run = 0;
        #pragma unroll
        for (int w = 0; w < 4; w++) { int v = warp_tot[w]; warp_tot[w] = run; run += v; }
        warp_tot[4] = run;
    }
    __syncthreads();
    int off = (inc - cnt) + warp_tot[wid];
    int base = t * 32;
    #pragma unroll
    for (int w = 0; w < 8; w++) {
        #pragma unroll
        for (int q = 0; q < 4; q++)
            if ((eq[w] >> (8 * q)) & 1u) flist[off++] = base + w * 4 + q;
    }
    __syncthreads();
    int M = warp_tot[4];
    if (M == 0) return;

    float offc = (float)c * MAX_WHF;   // exact in fp32

    if (M <= CAP) {
        // ---- Stage 2: build sort keys, pad, bitonic sort ----
        int P = 1; while (P < M) P <<= 1;
        for (int m = t; m < M; m += 128) {
            int idx = flist[m];
            unsigned int x = __float_as_uint(g_key[b * NN + idx]);
            x = (x & 0x80000000u) ? ~x : (x | 0x80000000u);
            skey[m] = ((unsigned long long)(~x) << 32) | (unsigned int)idx;
        }
        for (int m = M + t; m < P; m += 128) skey[m] = ~0ull;
        __syncthreads();
        for (int k = 2; k <= P; k <<= 1) {
            for (int j = k >> 1; j > 0; j >>= 1) {
                for (int p = t; p < (P >> 1); p += 128) {
                    int i   = ((p & ~(j - 1)) << 1) | (p & (j - 1));
                    int ixj = i | j;
                    bool up = ((i & k) == 0);
                    unsigned long long a = skey[i], d = skey[ixj];
                    if ((a > d) == up) { skey[i] = d; skey[ixj] = a; }
                }
                __syncthreads();
            }
        }

        // ---- Stage 3: unpack + gather member boxes into smem ----
        for (int m = t; m < M; m += 128) {
            int idx = (int)(skey[m] & 0xffffffffull);
            spos[m] = idx;
            scf[m]  = g_key[b * NN + idx];
            float4 bx = g_cbox[b * NN + idx];
            sx1[m] = bx.x; sy1[m] = bx.y; sx2[m] = bx.z; sy2[m] = bx.w;
            float ox1 = __fadd_rn(bx.x, offc), oy1 = __fadd_rn(bx.y, offc);
            float ox2 = __fadd_rn(bx.z, offc), oy2 = __fadd_rn(bx.w, offc);
            sar[m] = __fmul_rn(__fsub_rn(ox2, ox1), __fsub_rn(oy2, oy1));
        }
        __syncthreads();

        // ---- Stage 4: pairwise IoU>thr bit-matrix (independent rows) ----
        int W = (M + 31) >> 5;
        for (int i = wid; i < M; i += 4) {
            float ix1 = __fadd_rn(sx1[i], offc), iy1 = __fadd_rn(sy1[i], offc);
            float ix2 = __fadd_rn(sx2[i], offc), iy2 = __fadd_rn(sy2[i], offc);
            float ai  = sar[i];
            for (int cw = 0; cw < W; cw++) {
                int j = cw * 32 + lane;
                bool s = false;
                if (j < M && j > i) {
                    float jx1 = __fadd_rn(sx1[j], offc), jy1 = __fadd_rn(sy1[j], offc);
                    float jx2 = __fadd_rn(sx2[j], offc), jy2 = __fadd_rn(sy2[j], offc);
                    float aj  = sar[j];
                    float ltx = fmaxf(ix1, jx1), lty = fmaxf(iy1, jy1);
                    float rbx = fminf(ix2, jx2), rby = fminf(iy2, jy2);
                    float w = fmaxf(__fsub_rn(rbx, ltx), 0.0f);
                    float h = fmaxf(__fsub_rn(rby, lty), 0.0f);
                    float inter = __fmul_rn(w, h);
                    float denom = __fadd_rn(__fsub_rn(__fadd_rn(ai, aj), inter), 1e-9f);
                    s = __fdiv_rn(inter, denom) > IOU_THRF;
                }
                unsigned int bal = __ballot_sync(0xffffffffu, s);
                if (lane == 0) smask[i * WSTRIDE + cw] = bal;
            }
        }
        __syncthreads();

        // ---- Stage 5: greedy bitmask scan (scalar, tiny) ----
        if (t == 0) {
            unsigned int sup[WSTRIDE];
            #pragma unroll
            for (int w = 0; w < WSTRIDE; w++) sup[w] = 0;
            for (int i = 0; i < M; i++) {
                if ((sup[i >> 5] >> (i & 31)) & 1u) continue;
                int slot = atomicAdd(&g_kcnt[b], 1);
                float* kp = g_kept + ((size_t)b * NN + slot) * 8;
                kp[0] = sx1[i]; kp[1] = sy1[i]; kp[2] = sx2[i]; kp[3] = sy2[i];
                kp[4] = scf[i]; kp[5] = (float)c; kp[6] = (float)spos[i]; kp[7] = 0.0f;
                for (int w = 0; w < W; w++) sup[w] |= smask[i * WSTRIDE + w];
            }
        }
        return;
    }

    // ---- Fallback (M > CAP): selection-based greedy, correct but slow -------
    for (int m = t; m < M; m += 128) fsup[m] = 0;
    __syncthreads();
    for (;;) {
        float bk = -2.0f; int bm = -1; int bidx = 0x7fffffff;
        for (int m = t; m < M; m += 128) {
            if (fsup[m]) continue;
            int idx = flist[m];
            float kf = g_key[b * NN + idx];
            if (kf > bk || (kf == bk && idx < bidx)) { bk = kf; bm = m; bidx = idx; }
        }
        rbk[t] = bk; rbm[t] = bm;
        __syncthreads();
        if (t == 0) {
            float gbk = -2.0f; int gbm = -1; int gbidx = 0x7fffffff;
            for (int q = 0; q < 128; q++) {
                int m = rbm[q];
                if (m < 0) continue;
                int idx = flist[m];
                if (rbk[q] > gbk || (rbk[q] == gbk && idx < gbidx)) {
                    gbk = rbk[q]; gbm = m; gbidx = idx;
                }
            }
            bflag[0] = gbm;
            if (gbm >= 0) {
                fsup[gbm] = 1;
                float4 bx = g_cbox[b * NN + gbidx];
                int slot = atomicAdd(&g_kcnt[b], 1);
                float* kp = g_kept + ((size_t)b * NN + slot) * 8;
                kp[0] = bx.x; kp[1] = bx.y; kp[2] = bx.z; kp[3] = bx.w;
                kp[4] = gbk; kp[5] = (float)c; kp[6] = (float)gbidx; kp[7] = 0.0f;
                float ox1 = __fadd_rn(bx.x, offc), oy1 = __fadd_rn(bx.y, offc);
                float ox2 = __fadd_rn(bx.z, offc), oy2 = __fadd_rn(bx.w, offc);
                bbox[0] = ox1; bbox[1] = oy1; bbox[2] = ox2; bbox[3] = oy2;
                bbox[4] = __fmul_rn(__fsub_rn(ox2, ox1), __fsub_rn(oy2, oy1));
            }
        }
        __syncthreads();
        if (bflag[0] < 0) break;
        float ix1 = bbox[0], iy1 = bbox[1], ix2 = bbox[2], iy2 = bbox[3];
        float ai = bbox[4];
        for (int m = t; m < M; m += 128) {
            if (fsup[m]) continue;
            int idx = flist[m];
            float4 bx = g_cbox[b * NN + idx];
            float jx1 = __fadd_rn(bx.x, offc), jy1 = __fadd_rn(bx.y, offc);
            float jx2 = __fadd_rn(bx.z, offc), jy2 = __fadd_rn(bx.w, offc);
            float aj  = __fmul_rn(__fsub_rn(jx2, jx1), __fsub_rn(jy2, jy1));
            float ltx = fmaxf(ix1, jx1), lty = fmaxf(iy1, jy1);
            float rbx = fminf(ix2, jx2), rby = fminf(iy2, jy2);
            float w = fmaxf(__fsub_rn(rbx, ltx), 0.0f);
            float h = fmaxf(__fsub_rn(rby, lty), 0.0f);
            float inter = __fmul_rn(w, h);
            float denom = __fadd_rn(__fsub_rn(__fadd_rn(ai, aj), inter), 1e-9f);
            if (__fdiv_rn(inter, denom) > IOU_THRF) fsup[m] = 1;
        }
        __syncthreads();
    }
}

// ------------------------- K3: rank + scatter to output ---------------------
// rank(kept e) = #{j : key_j > key_e  or (key_j == key_e and j < idx_e)}
// == stable descending argsort position. Write 6-float row at that rank.
__global__ void __launch_bounds__(128) k3_rank(float* __restrict__ out) {
    int b = blockIdx.y;
    int t = threadIdx.x;
    int lane = t & 31, wid = t >> 5;
    __shared__ int wsum[4];
    int kc = g_kcnt[b];
    const float4* kr = reinterpret_cast<const float4*>(g_key + b * NN);

    for (int e = blockIdx.x; e < kc; e += gridDim.x) {
        const float* kp = g_kept + ((size_t)b * NN + e) * 8;
        float ke = kp[4];
        int  ide = (int)kp[6];
        int cnt = 0;
        #pragma unroll
        for (int f = t; f < NN / 4; f += 128) {
            float4 kv = kr[f];
            int j0 = f * 4;
            cnt += (kv.x > ke) || (kv.x == ke && (j0    ) < ide);
            cnt += (kv.y > ke) || (kv.y == ke && (j0 + 1) < ide);
            cnt += (kv.z > ke) || (kv.z == ke && (j0 + 2) < ide);
            cnt += (kv.w > ke) || (kv.w == ke && (j0 + 3) < ide);
        }
        #pragma unroll
        for (int o = 16; o > 0; o >>= 1)
            cnt += __shfl_down_sync(0xffffffffu, cnt, o);
        if (lane == 0) wsum[wid] = cnt;
        __syncthreads();
        if (t == 0) {
            int rank = wsum[0] + wsum[1] + wsum[2] + wsum[3];
            float* o = out + ((size_t)b * NN + rank) * 6;
            o[0] = kp[0]; o[1] = kp[1]; o[2] = kp[2]; o[3] = kp[3];
            o[4] = kp[4]; o[5] = kp[5];
        }
        __syncthreads();
    }
}

// ------------------------- launch -------------------------------------------
extern "C" void kernel_launch(void* const* d_in, const int* in_sizes, int n_in,
                              void* d_out, int out_size) {
    const float *boxes = nullptr, *scores = nullptr, *preds = nullptr;
    for (int i = 0; i < n_in; i++) {
        if (in_sizes[i] == BN * 4)       boxes  = (const float*)d_in[i];
        else if (in_sizes[i] == BN)      scores = (const float*)d_in[i];
        else if (in_sizes[i] == BN * CC) preds  = (const float*)d_in[i];
    }
    float* out = (float*)d_out;

    k0_zero<<<(out_size + 1023) / 1024, 1024>>>(out, out_size);
    k1_prepare<<<(BN * 32) / 1024, 1024>>>(boxes, scores, preds);
    k2_nms<<<BB * CC, 128>>>();
    dim3 g3(64, BB);
    k3_rank<<<g3, 128>>>(out);
}

// round 4
// speedup vs baseline: 1.2087x; 1.2087x over previous
#include <cuda_runtime.h>
#include <cuda_bf16.h>
#include <cstdint>

// Problem constants
#define BB 4
#define NN 4096
#define CC 64
#define BN (BB * NN)

#define TARGETF 560.0f
#define MIN_BOXF 5.0f
#define IOU_THRF 0.2f
#define CONF_THRF 0.001f
#define BOX_CONF_THRF 0.01f
#define MAX_WHF 4096.0f

#define CAP 256                    // per-class member cap for fast path
#define WSTRIDE 8                  // mask words per row (CAP/32)

// ------------------------- scratch (static device memory) -------------------
__device__ float4 g_cbox[BN];                      // clipped boxes, orig order
__device__ float  g_key[BN];                       // valid ? conf : -1
__device__ __align__(128) unsigned char g_tag[BN]; // valid ? cls : 255
__device__ float  g_kept[BB * NN * 8];             // kept entries (8 floats)
__device__ int    g_kcnt[BB];

// ------------------------- K0: zero output + counters -----------------------
__global__ void k0_zero(float* out, int n) {
    int i = blockIdx.x * blockDim.x + threadIdx.x;
    if (i < n) out[i] = 0.0f;
    if (i < BB) g_kcnt[i] = 0;
}

// ------------------------- K1: conf / argmax / clip / valid -----------------
__global__ void k1_prepare(const float* __restrict__ boxes,
                           const float* __restrict__ scores,
                           const float* __restrict__ preds) {
    int box  = (blockIdx.x * blockDim.x + threadIdx.x) >> 5;
    int lane = threadIdx.x & 31;
    if (box >= BN) return;

    const float* p = preds + (size_t)box * CC;
    float s = scores[box];

    float v0 = __fmul_rn(p[lane], s);
    float v1 = __fmul_rn(p[lane + 32], s);
    float bv; int bi;
    if (v1 > v0) { bv = v1; bi = lane + 32; } else { bv = v0; bi = lane; }

    #pragma unroll
    for (int o = 16; o > 0; o >>= 1) {
        float ov = __shfl_down_sync(0xffffffffu, bv, o);
        int   oi = __shfl_down_sync(0xffffffffu, bi, o);
        if (ov > bv || (ov == bv && oi < bi)) { bv = ov; bi = oi; }
    }

    if (lane == 0) {
        float4 bx = reinterpret_cast<const float4*>(boxes)[box];
        float x1 = fminf(fmaxf(bx.x, 0.0f), TARGETF);
        float y1 = fminf(fmaxf(bx.y, 0.0f), TARGETF);
        float x2 = fminf(fmaxf(bx.z, 0.0f), TARGETF);
        float y2 = fminf(fmaxf(bx.w, 0.0f), TARGETF);
        float w = __fsub_rn(x2, x1);
        float h = __fsub_rn(y2, y1);
        int valid = (s > BOX_CONF_THRF) && (w > MIN_BOXF) && (h > MIN_BOXF)
                    && (bv > CONF_THRF);
        g_cbox[box] = make_float4(x1, y1, x2, y2);
        g_key[box]  = valid ? bv : -1.0f;
        g_tag[box]  = valid ? (unsigned char)bi : (unsigned char)255;
    }
}

// ------------------------- K2: per-(batch,class) NMS ------------------------
// 128 threads. Compact members (original idx order) -> local stable sort by
// (conf desc, idx asc) -> smem-resident pairwise IoU bit-matrix -> greedy
// bitmask scan -> append kept entries to g_kept via atomic slot.
__global__ void __launch_bounds__(128) k2_nms() {
    int bc   = blockIdx.x;
    int b    = bc >> 6;
    int c    = bc & 63;
    int t    = threadIdx.x;
    int lane = t & 31;
    int wid  = t >> 5;

    __shared__ unsigned long long skey[CAP];                  // 2KB
    __shared__ float sx1[CAP], sy1[CAP], sx2[CAP], sy2[CAP];  // 4KB
    __shared__ float sar[CAP], scf[CAP];                      // 2KB
    __shared__ int   spos[CAP];                               // 1KB
    __shared__ unsigned int smask[CAP * WSTRIDE];             // 8KB
    __shared__ int   flist[NN];                               // 16KB (full list)
    __shared__ unsigned char fsup[NN];                        // 4KB (fallback)
    __shared__ int   warp_tot[5];
    __shared__ float rbk[128]; __shared__ int rbm[128];       // fallback reduce
    __shared__ float bbox[8];  __shared__ int bflag[1];

    // ---- Stage 1: compaction (thread t covers positions [t*32, t*32+32)) ---
    const uint4* tw = reinterpret_cast<const uint4*>(g_tag + b * NN);
    uint4 wa = tw[t * 2], wb = tw[t * 2 + 1];
    unsigned int cls4 = (unsigned int)c * 0x01010101u;
    unsigned int eq[8];
    eq[0] = __vcmpeq4(wa.x, cls4); eq[1] = __vcmpeq4(wa.y, cls4);
    eq[2] = __vcmpeq4(wa.z, cls4); eq[3] = __vcmpeq4(wa.w, cls4);
    eq[4] = __vcmpeq4(wb.x, cls4); eq[5] = __vcmpeq4(wb.y, cls4);
    eq[6] = __vcmpeq4(wb.z, cls4); eq[7] = __vcmpeq4(wb.w, cls4);
    int cnt = 0;
    #pragma unroll
    for (int w = 0; w < 8; w++) cnt += __popc(eq[w]) >> 3;

    // block exclusive scan
    int inc = cnt;
    #pragma unroll
    for (int o = 1; o < 32; o <<= 1) {
        int tmp = __shfl_up_sync(0xffffffffu, inc, o);
        if (lane >= o) inc += tmp;
    }
    if (lane == 31) warp_tot[wid] = inc;
    __syncthreads();
    if (t == 0) {
        int run = 0;
        #pragma unroll
        for (int w = 0; w < 4; w++) { int v = warp_tot[w]; warp_tot[w] = run; run += v; }
        warp_tot[4] = run;
    }
    __syncthreads();
    int off = (inc - cnt) + warp_tot[wid];
    int base = t * 32;
    #pragma unroll
    for (int w = 0; w < 8; w++) {
        #pragma unroll
        for (int q = 0; q < 4; q++)
            if ((eq[w] >> (8 * q)) & 1u) flist[off++] = base + w * 4 + q;
    }
    __syncthreads();
    int M = warp_tot[4];
    if (M == 0) return;

    float offc = (float)c * MAX_WHF;   // exact in fp32

    if (M <= CAP) {
        // ---- Stage 2: build sort keys, pad, bitonic sort ----
        int P = 1; while (P < M) P <<= 1;
        for (int m = t; m < M; m += 128) {
            int idx = flist[m];
            unsigned int x = __float_as_uint(g_key[b * NN + idx]);
            x = (x & 0x80000000u) ? ~x : (x | 0x80000000u);
            skey[m] = ((unsigned long long)(~x) << 32) | (unsigned int)idx;
        }
        for (int m = M + t; m < P; m += 128) skey[m] = ~0ull;
        __syncthreads();
        for (int k = 2; k <= P; k <<= 1) {
            for (int j = k >> 1; j > 0; j >>= 1) {
                for (int p = t; p < (P >> 1); p += 128) {
                    int i   = ((p & ~(j - 1)) << 1) | (p & (j - 1));
                    int ixj = i | j;
                    bool up = ((i & k) == 0);
                    unsigned long long a = skey[i], d = skey[ixj];
                    if ((a > d) == up) { skey[i] = d; skey[ixj] = a; }
                }
                __syncthreads();
            }
        }

        // ---- Stage 3: unpack + gather member boxes into smem ----
        for (int m = t; m < M; m += 128) {
            int idx = (int)(skey[m] & 0xffffffffull);
            spos[m] = idx;
            scf[m]  = g_key[b * NN + idx];
            float4 bx = g_cbox[b * NN + idx];
            sx1[m] = bx.x; sy1[m] = bx.y; sx2[m] = bx.z; sy2[m] = bx.w;
            float ox1 = __fadd_rn(bx.x, offc), oy1 = __fadd_rn(bx.y, offc);
            float ox2 = __fadd_rn(bx.z, offc), oy2 = __fadd_rn(bx.w, offc);
            sar[m] = __fmul_rn(__fsub_rn(ox2, ox1), __fsub_rn(oy2, oy1));
        }
        __syncthreads();

        // ---- Stage 4: pairwise IoU>thr bit-matrix (independent rows) ----
        int W = (M + 31) >> 5;
        for (int i = wid; i < M; i += 4) {
            float ix1 = __fadd_rn(sx1[i], offc), iy1 = __fadd_rn(sy1[i], offc);
            float ix2 = __fadd_rn(sx2[i], offc), iy2 = __fadd_rn(sy2[i], offc);
            float ai  = sar[i];
            for (int cw = 0; cw < W; cw++) {
                int j = cw * 32 + lane;
                bool s = false;
                if (j < M && j > i) {
                    float jx1 = __fadd_rn(sx1[j], offc), jy1 = __fadd_rn(sy1[j], offc);
                    float jx2 = __fadd_rn(sx2[j], offc), jy2 = __fadd_rn(sy2[j], offc);
                    float aj  = sar[j];
                    float ltx = fmaxf(ix1, jx1), lty = fmaxf(iy1, jy1);
                    float rbx = fminf(ix2, jx2), rby = fminf(iy2, jy2);
                    float w = fmaxf(__fsub_rn(rbx, ltx), 0.0f);
                    float h = fmaxf(__fsub_rn(rby, lty), 0.0f);
                    float inter = __fmul_rn(w, h);
                    float denom = __fadd_rn(__fsub_rn(__fadd_rn(ai, aj), inter), 1e-9f);
                    s = __fdiv_rn(inter, denom) > IOU_THRF;
                }
                unsigned int bal = __ballot_sync(0xffffffffu, s);
                if (lane == 0) smask[i * WSTRIDE + cw] = bal;
            }
        }
        __syncthreads();

        // ---- Stage 5: greedy bitmask scan (scalar, tiny) ----
        if (t == 0) {
            unsigned int sup[WSTRIDE];
            #pragma unroll
            for (int w = 0; w < WSTRIDE; w++) sup[w] = 0;
            for (int i = 0; i < M; i++) {
                if ((sup[i >> 5] >> (i & 31)) & 1u) continue;
                int slot = atomicAdd(&g_kcnt[b], 1);
                float* kp = g_kept + ((size_t)b * NN + slot) * 8;
                kp[0] = sx1[i]; kp[1] = sy1[i]; kp[2] = sx2[i]; kp[3] = sy2[i];
                kp[4] = scf[i]; kp[5] = (float)c; kp[6] = (float)spos[i]; kp[7] = 0.0f;
                for (int w = 0; w < W; w++) sup[w] |= smask[i * WSTRIDE + w];
            }
        }
        return;
    }

    // ---- Fallback (M > CAP): selection-based greedy, correct but slow -------
    for (int m = t; m < M; m += 128) fsup[m] = 0;
    __syncthreads();
    for (;;) {
        float bk = -2.0f; int bm = -1; int bidx = 0x7fffffff;
        for (int m = t; m < M; m += 128) {
            if (fsup[m]) continue;
            int idx = flist[m];
            float kf = g_key[b * NN + idx];
            if (kf > bk || (kf == bk && idx < bidx)) { bk = kf; bm = m; bidx = idx; }
        }
        rbk[t] = bk; rbm[t] = bm;
        __syncthreads();
        if (t == 0) {
            float gbk = -2.0f; int gbm = -1; int gbidx = 0x7fffffff;
            for (int q = 0; q < 128; q++) {
                int m = rbm[q];
                if (m < 0) continue;
                int idx = flist[m];
                if (rbk[q] > gbk || (rbk[q] == gbk && idx < gbidx)) {
                    gbk = rbk[q]; gbm = m; gbidx = idx;
                }
            }
            bflag[0] = gbm;
            if (gbm >= 0) {
                fsup[gbm] = 1;
                float4 bx = g_cbox[b * NN + gbidx];
                int slot = atomicAdd(&g_kcnt[b], 1);
                float* kp = g_kept + ((size_t)b * NN + slot) * 8;
                kp[0] = bx.x; kp[1] = bx.y; kp[2] = bx.z; kp[3] = bx.w;
                kp[4] = gbk; kp[5] = (float)c; kp[6] = (float)gbidx; kp[7] = 0.0f;
                float ox1 = __fadd_rn(bx.x, offc), oy1 = __fadd_rn(bx.y, offc);
                float ox2 = __fadd_rn(bx.z, offc), oy2 = __fadd_rn(bx.w, offc);
                bbox[0] = ox1; bbox[1] = oy1; bbox[2] = ox2; bbox[3] = oy2;
                bbox[4] = __fmul_rn(__fsub_rn(ox2, ox1), __fsub_rn(oy2, oy1));
            }
        }
        __syncthreads();
        if (bflag[0] < 0) break;
        float ix1 = bbox[0], iy1 = bbox[1], ix2 = bbox[2], iy2 = bbox[3];
        float ai = bbox[4];
        for (int m = t; m < M; m += 128) {
            if (fsup[m]) continue;
            int idx = flist[m];
            float4 bx = g_cbox[b * NN + idx];
            float jx1 = __fadd_rn(bx.x, offc), jy1 = __fadd_rn(bx.y, offc);
            float jx2 = __fadd_rn(bx.z, offc), jy2 = __fadd_rn(bx.w, offc);
            float aj  = __fmul_rn(__fsub_rn(jx2, jx1), __fsub_rn(jy2, jy1));
            float ltx = fmaxf(ix1, jx1), lty = fmaxf(iy1, jy1);
            float rbx = fminf(ix2, jx2), rby = fminf(iy2, jy2);
            float w = fmaxf(__fsub_rn(rbx, ltx), 0.0f);
            float h = fmaxf(__fsub_rn(rby, lty), 0.0f);
            float inter = __fmul_rn(w, h);
            float denom = __fadd_rn(__fsub_rn(__fadd_rn(ai, aj), inter), 1e-9f);
            if (__fdiv_rn(inter, denom) > IOU_THRF) fsup[m] = 1;
        }
        __syncthreads();
    }
}

// ------------------------- K3: rank + scatter to output ---------------------
// Keys cached in smem once per block; one WARP per kept entry (8 in flight
// per block, no barriers in the entry loop).
// rank(e) = #{j : key_j > key_e or (key_j == key_e and j < idx_e)}
__global__ void __launch_bounds__(256) k3_rank(float* __restrict__ out) {
    int b    = blockIdx.y;
    int t    = threadIdx.x;
    int lane = t & 31;
    int wid  = t >> 5;

    __shared__ float sk[NN];
    const float4* kr = reinterpret_cast<const float4*>(g_key + b * NN);
    #pragma unroll
    for (int f = t; f < NN / 4; f += 256) {
        float4 v = kr[f];
        sk[f * 4]     = v.x; sk[f * 4 + 1] = v.y;
        sk[f * 4 + 2] = v.z; sk[f * 4 + 3] = v.w;
    }
    __syncthreads();

    int kc = g_kcnt[b];
    for (int e = blockIdx.x * 8 + wid; e < kc; e += gridDim.x * 8) {
        const float* kp = g_kept + ((size_t)b * NN + e) * 8;
        float ke  = kp[4];
        int   ide = (int)kp[6];
        int cnt = 0;
        const float4* s4 = reinterpret_cast<const float4*>(sk);
        #pragma unroll 8
        for (int f = lane; f < NN / 4; f += 32) {
            float4 kv = s4[f];
            int j0 = f * 4;
            cnt += (kv.x > ke) || (kv.x == ke && (j0    ) < ide);
            cnt += (kv.y > ke) || (kv.y == ke && (j0 + 1) < ide);
            cnt += (kv.z > ke) || (kv.z == ke && (j0 + 2) < ide);
            cnt += (kv.w > ke) || (kv.w == ke && (j0 + 3) < ide);
        }
        #pragma unroll
        for (int o = 16; o > 0; o >>= 1)
            cnt += __shfl_down_sync(0xffffffffu, cnt, o);
        if (lane == 0) {
            float* o = out + ((size_t)b * NN + cnt) * 6;
            o[0] = kp[0]; o[1] = kp[1]; o[2] = kp[2]; o[3] = kp[3];
            o[4] = kp[4]; o[5] = kp[5];
        }
    }
}

// ------------------------- launch -------------------------------------------
extern "C" void kernel_launch(void* const* d_in, const int* in_sizes, int n_in,
                              void* d_out, int out_size) {
    const float *boxes = nullptr, *scores = nullptr, *preds = nullptr;
    for (int i = 0; i < n_in; i++) {
        if (in_sizes[i] == BN * 4)       boxes  = (const float*)d_in[i];
        else if (in_sizes[i] == BN)      scores = (const float*)d_in[i];
        else if (in_sizes[i] == BN * CC) preds  = (const float*)d_in[i];
    }
    float* out = (float*)d_out;

    k0_zero<<<(out_size + 1023) / 1024, 1024>>>(out, out_size);
    k1_prepare<<<(BN * 32) / 1024, 1024>>>(boxes, scores, preds);
    k2_nms<<<BB * CC, 128>>>();
    dim3 g3(32, BB);
    k3_rank<<<g3, 256>>>(out);
}

// round 5
// speedup vs baseline: 1.7721x; 1.4661x over previous
#include <cuda_runtime.h>
#include <cuda_bf16.h>
#include <cstdint>

// Problem constants
#define BB 4
#define NN 4096
#define CC 64
#define BN (BB * NN)

#define TARGETF 560.0f
#define MIN_BOXF 5.0f
#define IOU_THRF 0.2f
#define CONF_THRF 0.001f
#define BOX_CONF_THRF 0.01f
#define MAX_WHF 4096.0f

#define CAP 256                    // per-class member cap for fast path
#define WSTRIDE 8                  // mask words per row (CAP/32)

// ------------------------- scratch (static device memory) -------------------
__device__ float4 g_cbox[BN];                      // clipped boxes, orig order
__device__ float  g_key[BN];                       // valid ? conf : -1
__device__ __align__(128) unsigned char g_tag[BN]; // valid ? cls : 255
__device__ float  g_kept[BB * NN * 8];             // kept entries (8 floats)
__device__ int    g_kcnt[BB];

// ------------------------- K0: zero output + counters -----------------------
__global__ void k0_zero(float* out, int n) {
    int i = blockIdx.x * blockDim.x + threadIdx.x;
    if (i < n) out[i] = 0.0f;
    if (i < BB) g_kcnt[i] = 0;
}

// ------------------------- K1: conf / argmax / clip / valid -----------------
__global__ void k1_prepare(const float* __restrict__ boxes,
                           const float* __restrict__ scores,
                           const float* __restrict__ preds) {
    int box  = (blockIdx.x * blockDim.x + threadIdx.x) >> 5;
    int lane = threadIdx.x & 31;
    if (box >= BN) return;

    const float* p = preds + (size_t)box * CC;
    float s = scores[box];

    float v0 = __fmul_rn(p[lane], s);
    float v1 = __fmul_rn(p[lane + 32], s);
    float bv; int bi;
    if (v1 > v0) { bv = v1; bi = lane + 32; } else { bv = v0; bi = lane; }

    #pragma unroll
    for (int o = 16; o > 0; o >>= 1) {
        float ov = __shfl_down_sync(0xffffffffu, bv, o);
        int   oi = __shfl_down_sync(0xffffffffu, bi, o);
        if (ov > bv || (ov == bv && oi < bi)) { bv = ov; bi = oi; }
    }

    if (lane == 0) {
        float4 bx = reinterpret_cast<const float4*>(boxes)[box];
        float x1 = fminf(fmaxf(bx.x, 0.0f), TARGETF);
        float y1 = fminf(fmaxf(bx.y, 0.0f), TARGETF);
        float x2 = fminf(fmaxf(bx.z, 0.0f), TARGETF);
        float y2 = fminf(fmaxf(bx.w, 0.0f), TARGETF);
        float w = __fsub_rn(x2, x1);
        float h = __fsub_rn(y2, y1);
        int valid = (s > BOX_CONF_THRF) && (w > MIN_BOXF) && (h > MIN_BOXF)
                    && (bv > CONF_THRF);
        g_cbox[box] = make_float4(x1, y1, x2, y2);
        g_key[box]  = valid ? bv : -1.0f;
        g_tag[box]  = valid ? (unsigned char)bi : (unsigned char)255;
    }
}

// ------------------------- helpers for register bitonic --------------------
__device__ __forceinline__ unsigned long long kmin(unsigned long long a,
                                                   unsigned long long b) {
    return a < b ? a : b;
}
__device__ __forceinline__ unsigned long long kmax(unsigned long long a,
                                                   unsigned long long b) {
    return a > b ? a : b;
}
__device__ __forceinline__ void stage_j(unsigned long long v[4], int i0,
                                        int lane, int k, int j) {
    if (j >= 4) {
        int m = j >> 2;
        #pragma unroll
        for (int r = 0; r < 4; r++) {
            unsigned long long other = __shfl_xor_sync(0xffffffffu, v[r], m);
            bool up = (((i0 + r) & k) == 0);
            bool keepmin = (((lane & m) == 0) == up);
            v[r] = keepmin ? kmin(v[r], other) : kmax(v[r], other);
        }
    } else if (j == 2) {
        #pragma unroll
        for (int r = 0; r < 2; r++) {
            bool up = (((i0 + r) & k) == 0);
            unsigned long long a = v[r], c = v[r + 2];
            if ((a > c) == up) { v[r] = c; v[r + 2] = a; }
        }
    } else {
        #pragma unroll
        for (int r = 0; r < 4; r += 2) {
            bool up = (((i0 + r) & k) == 0);
            unsigned long long a = v[r], c = v[r + 1];
            if ((a > c) == up) { v[r] = c; v[r + 1] = a; }
        }
    }
}

// ------------------------- K2: per-(batch,class) NMS ------------------------
__global__ void __launch_bounds__(128) k2_nms() {
    int bc   = blockIdx.x;
    int b    = bc >> 6;
    int c    = bc & 63;
    int t    = threadIdx.x;
    int lane = t & 31;
    int wid  = t >> 5;

    __shared__ unsigned long long skey[CAP];                  // 2KB
    __shared__ float sx1[CAP], sy1[CAP], sx2[CAP], sy2[CAP];  // 4KB
    __shared__ float sar[CAP], scf[CAP];                      // 2KB
    __shared__ int   spos[CAP];                               // 1KB
    __shared__ unsigned int smask[CAP * WSTRIDE];             // 8KB
    __shared__ int   flist[NN];                               // 16KB
    __shared__ unsigned char fsup[NN];                        // 4KB (fallback)
    __shared__ int   warp_tot[5];
    __shared__ unsigned int keepw[WSTRIDE];
    __shared__ int   sbase;
    __shared__ float rbk[128]; __shared__ int rbm[128];       // fallback
    __shared__ float bbox[8];  __shared__ int bflag[1];

    // ---- Stage 1: compaction ----
    const uint4* tw = reinterpret_cast<const uint4*>(g_tag + b * NN);
    uint4 wa = tw[t * 2], wb = tw[t * 2 + 1];
    unsigned int cls4 = (unsigned int)c * 0x01010101u;
    unsigned int eq[8];
    eq[0] = __vcmpeq4(wa.x, cls4); eq[1] = __vcmpeq4(wa.y, cls4);
    eq[2] = __vcmpeq4(wa.z, cls4); eq[3] = __vcmpeq4(wa.w, cls4);
    eq[4] = __vcmpeq4(wb.x, cls4); eq[5] = __vcmpeq4(wb.y, cls4);
    eq[6] = __vcmpeq4(wb.z, cls4); eq[7] = __vcmpeq4(wb.w, cls4);
    int cnt = 0;
    #pragma unroll
    for (int w = 0; w < 8; w++) cnt += __popc(eq[w]) >> 3;

    int inc = cnt;
    #pragma unroll
    for (int o = 1; o < 32; o <<= 1) {
        int tmp = __shfl_up_sync(0xffffffffu, inc, o);
        if (lane >= o) inc += tmp;
    }
    if (lane == 31) warp_tot[wid] = inc;
    __syncthreads();
    if (t == 0) {
        int run = 0;
        #pragma unroll
        for (int w = 0; w < 4; w++) { int v = warp_tot[w]; warp_tot[w] = run; run += v; }
        warp_tot[4] = run;
    }
    __syncthreads();
    int off = (inc - cnt) + warp_tot[wid];
    int base = t * 32;
    #pragma unroll
    for (int w = 0; w < 8; w++) {
        #pragma unroll
        for (int q = 0; q < 4; q++)
            if ((eq[w] >> (8 * q)) & 1u) flist[off++] = base + w * 4 + q;
    }
    __syncthreads();
    int M = warp_tot[4];
    if (M == 0) return;

    float offc = (float)c * MAX_WHF;   // exact in fp32

    if (M <= CAP) {
        // ---- Stage 2: stable sort by (conf desc, idx asc) ----
        if (M <= 128) {
            // pad to 128, barrier-free register bitonic in warp 0
            if (t < 128) {
                unsigned long long kv = ~0ull;
                if (t < M) {
                    int idx = flist[t];
                    unsigned int x = __float_as_uint(g_key[b * NN + idx]);
                    x = (x & 0x80000000u) ? ~x : (x | 0x80000000u);
                    kv = ((unsigned long long)(~x) << 32) | (unsigned int)idx;
                }
                skey[t] = kv;
            }
            __syncthreads();
            if (wid == 0) {
                unsigned long long v[4];
                int i0 = lane << 2;
                #pragma unroll
                for (int r = 0; r < 4; r++) v[r] = skey[i0 + r];
                #pragma unroll
                for (int k = 2; k <= 128; k <<= 1)
                    for (int j = k >> 1; j >= 1; j >>= 1)
                        stage_j(v, i0, lane, k, j);
                #pragma unroll
                for (int r = 0; r < 4; r++) skey[i0 + r] = v[r];
            }
            __syncthreads();
        } else {
            int P = CAP;
            for (int m = t; m < M; m += 128) {
                int idx = flist[m];
                unsigned int x = __float_as_uint(g_key[b * NN + idx]);
                x = (x & 0x80000000u) ? ~x : (x | 0x80000000u);
                skey[m] = ((unsigned long long)(~x) << 32) | (unsigned int)idx;
            }
            for (int m = M + t; m < P; m += 128) skey[m] = ~0ull;
            __syncthreads();
            for (int k = 2; k <= P; k <<= 1) {
                for (int j = k >> 1; j > 0; j >>= 1) {
                    for (int p = t; p < (P >> 1); p += 128) {
                        int i   = ((p & ~(j - 1)) << 1) | (p & (j - 1));
                        int ixj = i | j;
                        bool up = ((i & k) == 0);
                        unsigned long long a = skey[i], d = skey[ixj];
                        if ((a > d) == up) { skey[i] = d; skey[ixj] = a; }
                    }
                    __syncthreads();
                }
            }
        }

        // ---- Stage 3: unpack + gather member boxes into smem ----
        for (int m = t; m < M; m += 128) {
            int idx = (int)(skey[m] & 0xffffffffull);
            spos[m] = idx;
            scf[m]  = g_key[b * NN + idx];
            float4 bx = g_cbox[b * NN + idx];
            sx1[m] = bx.x; sy1[m] = bx.y; sx2[m] = bx.z; sy2[m] = bx.w;
            float ox1 = __fadd_rn(bx.x, offc), oy1 = __fadd_rn(bx.y, offc);
            float ox2 = __fadd_rn(bx.z, offc), oy2 = __fadd_rn(bx.w, offc);
            sar[m] = __fmul_rn(__fsub_rn(ox2, ox1), __fsub_rn(oy2, oy1));
        }
        __syncthreads();

        // ---- Stage 4: pairwise IoU>thr bit-matrix ----
        int W = (M + 31) >> 5;
        for (int i = wid; i < M; i += 4) {
            float ix1 = __fadd_rn(sx1[i], offc), iy1 = __fadd_rn(sy1[i], offc);
            float ix2 = __fadd_rn(sx2[i], offc), iy2 = __fadd_rn(sy2[i], offc);
            float ai  = sar[i];
            for (int cw = 0; cw < W; cw++) {
                int j = cw * 32 + lane;
                bool s = false;
                if (j < M && j > i) {
                    float jx1 = __fadd_rn(sx1[j], offc), jy1 = __fadd_rn(sy1[j], offc);
                    float jx2 = __fadd_rn(sx2[j], offc), jy2 = __fadd_rn(sy2[j], offc);
                    float aj  = sar[j];
                    float ltx = fmaxf(ix1, jx1), lty = fmaxf(iy1, jy1);
                    float rbx = fminf(ix2, jx2), rby = fminf(iy2, jy2);
                    float w = fmaxf(__fsub_rn(rbx, ltx), 0.0f);
                    float h = fmaxf(__fsub_rn(rby, lty), 0.0f);
                    float inter = __fmul_rn(w, h);
                    float denom = __fadd_rn(__fsub_rn(__fadd_rn(ai, aj), inter), 1e-9f);
                    s = __fdiv_rn(inter, denom) > IOU_THRF;
                }
                unsigned int bal = __ballot_sync(0xffffffffu, s);
                if (lane == 0) smask[i * WSTRIDE + cw] = bal;
            }
        }
        __syncthreads();

        // ---- Stage 5a: keep-mask scan (thread 0, no globals in loop) ----
        if (t == 0) {
            unsigned int sup[WSTRIDE], keep[WSTRIDE];
            #pragma unroll
            for (int w = 0; w < WSTRIDE; w++) { sup[w] = 0; keep[w] = 0; }
            int nk = 0;
            for (int i = 0; i < M; i++) {
                if ((sup[i >> 5] >> (i & 31)) & 1u) continue;
                keep[i >> 5] |= (1u << (i & 31));
                nk++;
                for (int w = 0; w < W; w++) sup[w] |= smask[i * WSTRIDE + w];
            }
            #pragma unroll
            for (int w = 0; w < WSTRIDE; w++) keepw[w] = keep[w];
            sbase = atomicAdd(&g_kcnt[b], nk);
        }
        __syncthreads();

        // ---- Stage 5b: parallel scatter of kept entries ----
        int kb = sbase;
        for (int m = t; m < M; m += 128) {
            if ((keepw[m >> 5] >> (m & 31)) & 1u) {
                int pre = __popc(keepw[m >> 5] & ((1u << (m & 31)) - 1u));
                for (int w = 0; w < (m >> 5); w++) pre += __popc(keepw[w]);
                float* kp = g_kept + ((size_t)b * NN + kb + pre) * 8;
                kp[0] = sx1[m]; kp[1] = sy1[m]; kp[2] = sx2[m]; kp[3] = sy2[m];
                kp[4] = scf[m]; kp[5] = (float)c; kp[6] = (float)spos[m];
                kp[7] = 0.0f;
            }
        }
        return;
    }

    // ---- Fallback (M > CAP): selection-based greedy, correct but slow ------
    for (int m = t; m < M; m += 128) fsup[m] = 0;
    __syncthreads();
    for (;;) {
        float bk = -2.0f; int bm = -1; int bidx = 0x7fffffff;
        for (int m = t; m < M; m += 128) {
            if (fsup[m]) continue;
            int idx = flist[m];
            float kf = g_key[b * NN + idx];
            if (kf > bk || (kf == bk && idx < bidx)) { bk = kf; bm = m; bidx = idx; }
        }
        rbk[t] = bk; rbm[t] = bm;
        __syncthreads();
        if (t == 0) {
            float gbk = -2.0f; int gbm = -1; int gbidx = 0x7fffffff;
            for (int q = 0; q < 128; q++) {
                int m = rbm[q];
                if (m < 0) continue;
                int idx = flist[m];
                if (rbk[q] > gbk || (rbk[q] == gbk && idx < gbidx)) {
                    gbk = rbk[q]; gbm = m; gbidx = idx;
                }
            }
            bflag[0] = gbm;
            if (gbm >= 0) {
                fsup[gbm] = 1;
                float4 bx = g_cbox[b * NN + gbidx];
                int slot = atomicAdd(&g_kcnt[b], 1);
                float* kp = g_kept + ((size_t)b * NN + slot) * 8;
                kp[0] = bx.x; kp[1] = bx.y; kp[2] = bx.z; kp[3] = bx.w;
                kp[4] = gbk; kp[5] = (float)c; kp[6] = (float)gbidx; kp[7] = 0.0f;
                float ox1 = __fadd_rn(bx.x, offc), oy1 = __fadd_rn(bx.y, offc);
                float ox2 = __fadd_rn(bx.z, offc), oy2 = __fadd_rn(bx.w, offc);
                bbox[0] = ox1; bbox[1] = oy1; bbox[2] = ox2; bbox[3] = oy2;
                bbox[4] = __fmul_rn(__fsub_rn(ox2, ox1), __fsub_rn(oy2, oy1));
            }
        }
        __syncthreads();
        if (bflag[0] < 0) break;
        float ix1 = bbox[0], iy1 = bbox[1], ix2 = bbox[2], iy2 = bbox[3];
        float ai = bbox[4];
        for (int m = t; m < M; m += 128) {
            if (fsup[m]) continue;
            int idx = flist[m];
            float4 bx = g_cbox[b * NN + idx];
            float jx1 = __fadd_rn(bx.x, offc), jy1 = __fadd_rn(bx.y, offc);
            float jx2 = __fadd_rn(bx.z, offc), jy2 = __fadd_rn(bx.w, offc);
            float aj  = __fmul_rn(__fsub_rn(jx2, jx1), __fsub_rn(jy2, jy1));
            float ltx = fmaxf(ix1, jx1), lty = fmaxf(iy1, jy1);
            float rbx = fminf(ix2, jx2), rby = fminf(iy2, jy2);
            float w = fmaxf(__fsub_rn(rbx, ltx), 0.0f);
            float h = fmaxf(__fsub_rn(rby, lty), 0.0f);
            float inter = __fmul_rn(w, h);
            float denom = __fadd_rn(__fsub_rn(__fadd_rn(ai, aj), inter), 1e-9f);
            if (__fdiv_rn(inter, denom) > IOU_THRF) fsup[m] = 1;
        }
        __syncthreads();
    }
}

// ------------------------- K3: rank + scatter to output ---------------------
// Composite u64 keys cached in smem; one warp per kept entry.
// K_j = (ordered(key_j)<<32) | (4095-j);  rank(e) = #{j : K_j > K_e}
__global__ void __launch_bounds__(256) k3_rank(float* __restrict__ out) {
    int b    = blockIdx.y;
    int t    = threadIdx.x;
    int lane = t & 31;
    int wid  = t >> 5;

    __shared__ unsigned long long sk[NN];   // 32KB
    const float4* kr = reinterpret_cast<const float4*>(g_key + b * NN);
    #pragma unroll
    for (int f = t; f < NN / 4; f += 256) {
        float4 v = kr[f];
        int j0 = f * 4;
        float vv[4] = {v.x, v.y, v.z, v.w};
        #pragma unroll
        for (int q = 0; q < 4; q++) {
            unsigned int x = __float_as_uint(vv[q]);
            x = (x & 0x80000000u) ? ~x : (x | 0x80000000u);
            sk[j0 + q] = ((unsigned long long)x << 32)
                       | (unsigned int)(NN - 1 - (j0 + q));
        }
    }
    __syncthreads();

    int kc = g_kcnt[b];
    const ulonglong2* s2 = reinterpret_cast<const ulonglong2*>(sk);
    for (int e = blockIdx.x * 8 + wid; e < kc; e += gridDim.x * 8) {
        const float* kp = g_kept + ((size_t)b * NN + e) * 8;
        float ke  = kp[4];
        int   ide = (int)kp[6];
        unsigned int x = __float_as_uint(ke);
        x = (x & 0x80000000u) ? ~x : (x | 0x80000000u);
        unsigned long long Ke = ((unsigned long long)x << 32)
                              | (unsigned int)(NN - 1 - ide);
        int cnt = 0;
        #pragma unroll 8
        for (int f = lane; f < NN / 2; f += 32) {
            ulonglong2 v = s2[f];
            cnt += (v.x > Ke);
            cnt += (v.y > Ke);
        }
        #pragma unroll
        for (int o = 16; o > 0; o >>= 1)
            cnt += __shfl_down_sync(0xffffffffu, cnt, o);
        if (lane == 0) {
            float* o = out + ((size_t)b * NN + cnt) * 6;
            o[0] = kp[0]; o[1] = kp[1]; o[2] = kp[2]; o[3] = kp[3];
            o[4] = kp[4]; o[5] = kp[5];
        }
    }
}

// ------------------------- launch -------------------------------------------
extern "C" void kernel_launch(void* const* d_in, const int* in_sizes, int n_in,
                              void* d_out, int out_size) {
    const float *boxes = nullptr, *scores = nullptr, *preds = nullptr;
    for (int i = 0; i < n_in; i++) {
        if (in_sizes[i] == BN * 4)       boxes  = (const float*)d_in[i];
        else if (in_sizes[i] == BN)      scores = (const float*)d_in[i];
        else if (in_sizes[i] == BN * CC) preds  = (const float*)d_in[i];
    }
    float* out = (float*)d_out;

    k0_zero<<<(out_size + 1023) / 1024, 1024>>>(out, out_size);
    k1_prepare<<<(BN * 32) / 1024, 1024>>>(boxes, scores, preds);
    k2_nms<<<BB * CC, 128>>>();
    dim3 g3(64, BB);
    k3_rank<<<g3, 256>>>(out);
}